// round 15
// baseline (speedup 1.0000x reference)
#include <cuda_runtime.h>
#include <math_constants.h>

// AutoCorrelation (Autoformer): q,k,v (32,8,2048,64) fp32.
// corr[r,d] = sum_j q[r,j]*k[r,(j-d)%64]; top-4 over d, softmax, gather v.
// out = [ V (B,H,L,E) | corr^T (B,E,H,L) ]
//
// FOUR lanes per row (quad = d-quarter of 16). k streams through a 16-deep
// rotating register window (compile-time slots); core live set wv16+c16=32
// regs -> fits launch_bounds(128,6)=85 -> 24 warps/SM (vs R14's 20 at 96).
// Gap swizzle scol = col + 8*(col>>4), stride 89: k-refill banks
// 25*row + 24*u + t are all-distinct across the warp (R14 had 2-way).

#define STRT 89
#define SW(c) ((c) + (((c) >> 4) << 3))    // col -> swizzled col

#define CP_ASYNC4(smem_u32, gptr) \
    asm volatile("cp.async.ca.shared.global [%0], [%1], 4;" \
                 :: "r"(smem_u32), "l"(gptr) : "memory")
#define CP_COMMIT() asm volatile("cp.async.commit_group;" ::: "memory")
#define CP_WAIT0()  asm volatile("cp.async.wait_group 0;" ::: "memory")

// topk insert, strict > keeps lowest index on ties (lax.top_k order)
#define TOPK_INS(vv, d)                                                          \
    if (vv > w3) {                                                               \
        if (vv > w2) {                                                           \
            if (vv > w1) {                                                       \
                if (vv > w0) { w3=w2;i3=i2; w2=w1;i2=i1; w1=w0;i1=i0; w0=vv;i0=d;}\
                else          { w3=w2;i3=i2; w2=w1;i2=i1; w1=vv;i1=d; }          \
            } else            { w3=w2;i3=i2; w2=vv;i2=d; }                       \
        } else                { w3=vv;i3=d; }                                    \
    }

// merge round: a = list whose d-range is entirely lower (wins ties)
#define MSTEP(mo, mio) {                                                         \
    const bool ta = (a0 >= b0);                                                  \
    mo = ta ? a0 : b0; mio = ta ? ai0 : bi0;                                     \
    if (ta) { a0=a1; ai0=ai1; a1=a2; ai1=ai2; a2=a3; ai2=ai3; a3=-CUDART_INF_F; }\
    else    { b0=b1; bi0=bi1; b1=b2; bi1=bi2; b2=b3; bi2=bi3; b3=-CUDART_INF_F; }}

#define SHUF4(pv, pw, mask) \
    pv##0=__shfl_xor_sync(0xFFFFFFFFu,pw##0,mask); pv##1=__shfl_xor_sync(0xFFFFFFFFu,pw##1,mask); \
    pv##2=__shfl_xor_sync(0xFFFFFFFFu,pw##2,mask); pv##3=__shfl_xor_sync(0xFFFFFFFFu,pw##3,mask);

__global__ void __launch_bounds__(128, 6)
autocorr_kernel(const float* __restrict__ gq,
                const float* __restrict__ gk,
                const float* __restrict__ gv,
                float* __restrict__ outV,
                float* __restrict__ outC) {
    __shared__ float TQ[4][8][STRT];    // per-warp q tile, reused for v
    __shared__ float TK[4][8][STRT];    // per-warp k tile

    const int w    = threadIdx.x >> 5;
    const int lane = threadIdx.x & 31;
    const int row  = lane >> 2;          // 0..7
    const int quad = lane & 3;           // d-quarter selector
    const int d0   = quad << 4;          // 0,16,32,48

    float* Q = &TQ[w][0][0];
    float* K = &TK[w][0][0];
    const unsigned Qs = (unsigned)__cvta_generic_to_shared(Q);
    const unsigned Ks = (unsigned)__cvta_generic_to_shared(K);

    const unsigned rblk = (unsigned)blockIdx.x * 32u;        // block row base
    const unsigned rw   = rblk + (unsigned)w * 8u;           // warp row base
    const unsigned offw = rw * 64u;                          // element offset

    // async-stage 8 rows x 64 floats, swizzled cols (zero register cost)
#define ASTAGE(base_u32, gsrc)                                               \
    _Pragma("unroll 8")                                                      \
    for (int it = 0; it < 16; it++) {                                        \
        const int f   = it * 32 + lane;                                      \
        const int col = f & 63;                                              \
        const int fi  = (f >> 6) * STRT + SW(col);                           \
        CP_ASYNC4(base_u32 + 4u * (unsigned)fi, gsrc + offw + (unsigned)f);  \
    }

    ASTAGE(Ks, gk);
    ASTAGE(Qs, gq);
    CP_COMMIT(); CP_WAIT0();
    __syncwarp();

    const float* Krow = K + row * STRT;
    const float* Qrow = Q + row * STRT;

    // ---- rotating 16-deep k window (prologue: slots for j = -15..-1) ----
    float wv[16];
    #pragma unroll
    for (int t = -15; t < 0; t++)
        wv[(t + 16) & 15] = Krow[SW((t + 64 - d0) & 63)];

    float c[16];
    #pragma unroll
    for (int i = 0; i < 16; i++) c[i] = 0.f;

    #pragma unroll
    for (int j = 0; j < 64; j++) {
        wv[j & 15] = Krow[SW((j + 64 - d0) & 63)];   // conflict-free refill
        const float qj = Qrow[SW(j)];                 // broadcast per row
        #pragma unroll
        for (int dd = 0; dd < 16; dd++)               // c[dd] += q[j]*k[(j-d0-dd)&63]
            c[dd] = fmaf(qj, wv[(j - dd) & 15], c[dd]);
    }

    // ---- corr^T store + local top-4 over this thread's 16 d values ----
    const unsigned bb = rw >> 14;
    const unsigned hh = (rw >> 11) & 7u;
    const unsigned ll = (rw & 2047u) + (unsigned)row;
    float* cA = outC + bb * (64u * 8u * 2048u) + hh * 2048u + ll
                     + (unsigned)d0 * 16384u;

    float w0=-CUDART_INF_F, w1=-CUDART_INF_F, w2=-CUDART_INF_F, w3=-CUDART_INF_F;
    int   i0=0, i1=0, i2=0, i3=0;
    #pragma unroll
    for (int dd = 0; dd < 16; dd++) {
        const float v = c[dd];
        const int   d = d0 + dd;
        cA[(unsigned)dd * 16384u] = v;     // 8 contiguous l per (d): full 32B sectors
        TOPK_INS(v, d);
    }

    // ---- merge top-4 across the quad: round 1 (xor 1), round 2 (xor 2) ----
    float m0, m1, m2, m3; int mi0, mi1, mi2, mi3;
    {
        float p0,p1,p2,p3; int q0i,q1i,q2i,q3i;
        p0=__shfl_xor_sync(0xFFFFFFFFu,w0,1); p1=__shfl_xor_sync(0xFFFFFFFFu,w1,1);
        p2=__shfl_xor_sync(0xFFFFFFFFu,w2,1); p3=__shfl_xor_sync(0xFFFFFFFFu,w3,1);
        q0i=__shfl_xor_sync(0xFFFFFFFFu,i0,1); q1i=__shfl_xor_sync(0xFFFFFFFFu,i1,1);
        q2i=__shfl_xor_sync(0xFFFFFFFFu,i2,1); q3i=__shfl_xor_sync(0xFFFFFFFFu,i3,1);
        const bool hi = quad & 1;            // my list is the higher-d one
        float a0 = hi?p0:w0, a1 = hi?p1:w1, a2 = hi?p2:w2, a3 = hi?p3:w3;
        int  ai0 = hi?q0i:i0, ai1 = hi?q1i:i1, ai2 = hi?q2i:i2, ai3 = hi?q3i:i3;
        float b0 = hi?w0:p0, b1 = hi?w1:p1, b2 = hi?w2:p2, b3 = hi?w3:p3;
        int  bi0 = hi?i0:q0i, bi1 = hi?i1:q1i, bi2 = hi?i2:q2i, bi3 = hi?i3:q3i;
        MSTEP(m0,mi0) MSTEP(m1,mi1) MSTEP(m2,mi2) MSTEP(m3,mi3)
    }
    {
        float p0,p1,p2,p3; int q0i,q1i,q2i,q3i;
        p0=__shfl_xor_sync(0xFFFFFFFFu,m0,2); p1=__shfl_xor_sync(0xFFFFFFFFu,m1,2);
        p2=__shfl_xor_sync(0xFFFFFFFFu,m2,2); p3=__shfl_xor_sync(0xFFFFFFFFu,m3,2);
        q0i=__shfl_xor_sync(0xFFFFFFFFu,mi0,2); q1i=__shfl_xor_sync(0xFFFFFFFFu,mi1,2);
        q2i=__shfl_xor_sync(0xFFFFFFFFu,mi2,2); q3i=__shfl_xor_sync(0xFFFFFFFFu,mi3,2);
        const bool hi = (quad >> 1) & 1;
        float a0 = hi?p0:m0, a1 = hi?p1:m1, a2 = hi?p2:m2, a3 = hi?p3:m3;
        int  ai0 = hi?q0i:mi0, ai1 = hi?q1i:mi1, ai2 = hi?q2i:mi2, ai3 = hi?q3i:mi3;
        float b0 = hi?m0:p0, b1 = hi?m1:p1, b2 = hi?m2:p2, b3 = hi?m3:p3;
        int  bi0 = hi?mi0:q0i, bi1 = hi?mi1:q1i, bi2 = hi?mi2:q2i, bi3 = hi?mi3:q3i;
        MSTEP(m0,mi0) MSTEP(m1,mi1) MSTEP(m2,mi2) MSTEP(m3,mi3)
    }

    // ---- softmax over the 4 weights (m0 is the max) ----
    const float e1 = __expf(m1 - m0), e2 = __expf(m2 - m0), e3 = __expf(m3 - m0);
    const float inv = 1.f / (1.f + e1 + e2 + e3);
    const float t0 = inv, t1 = e1 * inv, t2 = e2 * inv, t3 = e3 * inv;

    // ---- v into the q tile (q dead) ----
    __syncwarp();
    ASTAGE(Qs, gv);
    CP_COMMIT(); CP_WAIT0();
    __syncwarp();

    // ---- gather: this thread covers e in [16*quad, 16*quad+16) of its row ----
    {
        const float* Vrow = Q + row * STRT;
        const int e0 = quad << 4;
        const int g0 = e0 + mi0, g1 = e0 + mi1, g2 = e0 + mi2, g3 = e0 + mi3;
        float* outR = outV + offw + (unsigned)(row * 64 + e0);
        #pragma unroll
        for (int eg = 0; eg < 4; eg++) {
            float4 o;
            #pragma unroll
            for (int s = 0; s < 4; s++) {
                const int e = eg * 4 + s;
                float sa =      t0 * Vrow[SW((g0 + e) & 63)];
                sa = fmaf(t1, Vrow[SW((g1 + e) & 63)], sa);
                sa = fmaf(t2, Vrow[SW((g2 + e) & 63)], sa);
                sa = fmaf(t3, Vrow[SW((g3 + e) & 63)], sa);
                (&o.x)[s] = sa;
            }
            *(float4*)(outR + eg * 4) = o;   // warp: 8 rows x 256B contiguous
        }
    }
}

extern "C" void kernel_launch(void* const* d_in, const int* in_sizes, int n_in,
                              void* d_out, int out_size) {
    const float* q = (const float*)d_in[0];
    const float* k = (const float*)d_in[1];
    const float* v = (const float*)d_in[2];
    float* outV = (float*)d_out;
    float* outC = (float*)d_out + (long long)32 * 8 * 2048 * 64;

    const int rows    = 32 * 8 * 2048;      // 524288
    const int nblocks = rows / 32;          // 16384 blocks: 4 warps x 8 rows
    autocorr_kernel<<<nblocks, 128>>>(q, k, v, outV, outC);
}